// round 7
// baseline (speedup 1.0000x reference)
#include <cuda_runtime.h>

// filtfilt(butter(4)) over 512 rows x 32768 fp32 samples.
// R7 = R5 geometry (2 segments/row, 128 IIR threads, 66KB smem, 3 blocks/SM)
// with the DF2T state packed into f32x2 pairs and updated via PTX
// fma.rn.f32x2 (FFMA2): 5 FMA-pipe ops/sample instead of 9. The fma pipe
// (rt_SMSP=2 for FFMA-3reg) was measured to be the binding resource.
// State: Zodd=(z1,z3), Zeven=(z2,z4);
//   y      = fma(b0,x,z1)                           (scalar, short chain)
//   Zodd'  = fma2(NA13, Y2, fma2(B13, X2, Zeven))
//   Zeven' = fma2(NA24, Y2, fma2(B24, X2, (z3,0)))
// Warm-up W=56 from zero state (max pole 0.795 -> residual ~3e-6).
// max|x| normalization skipped (linear pipeline; rounding-level change).

#define T_LEN  32768
#define PAD    15
#define TE     (T_LEN + 2 * PAD)   /* 32798 */
#define S      16399               /* split, ==3 mod 4 */
#define NTH    128
#define C      132
#define W      56
#define SMLEN  16480

#define B0f  0.0048243445989025905f
#define B1f  0.019297378395610362f
#define B2f  0.028946067593415543f
#define NA1f 2.369513007182038f      /* -a1 */
#define NA2f (-2.3139884144002064f)  /* -a2 */
#define NA3f 1.0546654058785661f     /* -a3 */
#define NA4f (-0.18737949236818502f) /* -a4 */

typedef unsigned long long u64;

__device__ __forceinline__ u64 packf2(float lo, float hi) {
    u64 r;
    asm("mov.b64 %0, {%1, %2};" : "=l"(r) : "f"(lo), "f"(hi));
    return r;
}
__device__ __forceinline__ u64 fma2(u64 a, u64 b, u64 c) {
    u64 r;
    asm("fma.rn.f32x2 %0, %1, %2, %3;" : "=l"(r) : "l"(a), "l"(b), "l"(c));
    return r;
}

struct StP { u64 zodd, zeven; };   // (z1,z3), (z2,z4)
struct Coef { u64 B13, B24, NA13, NA24; };

__device__ __forceinline__ float stepp(float x, StP& s, const Coef& k) {
    const float z1 = __uint_as_float((unsigned)(s.zodd));
    const float z3 = __uint_as_float((unsigned)(s.zodd >> 32));
    const float y  = fmaf(B0f, x, z1);
    const u64 X2 = packf2(x, x);
    const u64 Y2 = packf2(y, y);
    const u64 Z30 = packf2(z3, 0.0f);
    const u64 P = fma2(k.B13, X2, s.zeven);   // independent of y
    const u64 Q = fma2(k.B24, X2, Z30);
    s.zodd  = fma2(k.NA13, Y2, P);
    s.zeven = fma2(k.NA24, Y2, Q);
    return y;
}

// ascending over smem indices [i, end)
__device__ __forceinline__ void fwd_ro(const float* s, int i, int end, StP& st, const Coef& k) {
    for (; i < end && (i & 3); ++i) stepp(s[i], st, k);
    #pragma unroll 2
    for (; i + 4 <= end; i += 4) {
        float4 v = *(const float4*)(s + i);
        stepp(v.x, st, k); stepp(v.y, st, k); stepp(v.z, st, k); stepp(v.w, st, k);
    }
    for (; i < end; ++i) stepp(s[i], st, k);
}
__device__ __forceinline__ void fwd_rw(float* s, int i, int end, StP& st, const Coef& k) {
    for (; i < end && (i & 3); ++i) { s[i] = stepp(s[i], st, k); }
    #pragma unroll 2
    for (; i + 4 <= end; i += 4) {
        float4 v = *(float4*)(s + i);
        v.x = stepp(v.x, st, k); v.y = stepp(v.y, st, k);
        v.z = stepp(v.z, st, k); v.w = stepp(v.w, st, k);
        *(float4*)(s + i) = v;
    }
    for (; i < end; ++i) s[i] = stepp(s[i], st, k);
}
// descending over smem indices i down to lo (inclusive)
__device__ __forceinline__ void bwd_ro(const float* s, int i, int lo, StP& st, const Coef& k) {
    for (; i >= lo && ((i & 3) != 3); --i) stepp(s[i], st, k);
    #pragma unroll 2
    for (; i - 3 >= lo; i -= 4) {
        float4 v = *(const float4*)(s + i - 3);
        stepp(v.w, st, k); stepp(v.z, st, k); stepp(v.y, st, k); stepp(v.x, st, k);
    }
    for (; i >= lo; --i) stepp(s[i], st, k);
}
__device__ __forceinline__ void bwd_rw(float* s, int i, int lo, StP& st, const Coef& k) {
    for (; i >= lo && ((i & 3) != 3); --i) { s[i] = stepp(s[i], st, k); }
    #pragma unroll 2
    for (; i - 3 >= lo; i -= 4) {
        float4 v = *(float4*)(s + i - 3);
        v.w = stepp(v.w, st, k); v.z = stepp(v.z, st, k);
        v.y = stepp(v.y, st, k); v.x = stepp(v.x, st, k);
        *(float4*)(s + i - 3) = v;
    }
    for (; i >= lo; --i) s[i] = stepp(s[i], st, k);
}

__global__ void __launch_bounds__(NTH)
filtfilt_r7_kernel(const float* __restrict__ x, float* __restrict__ out) {
    extern __shared__ float sm[];
    const int tid = threadIdx.x;
    const int row = blockIdx.x >> 1;
    const int seg = blockIdx.x & 1;
    const float* __restrict__ xr = x + (size_t)row * T_LEN;

    Coef cf;
    cf.B13  = packf2(B1f,  B1f);    // b3 == b1
    cf.B24  = packf2(B2f,  B0f);    // b4 == b0
    cf.NA13 = packf2(NA1f, NA3f);
    cf.NA24 = packf2(NA2f, NA4f);

    // qoff: xe(e) = sm[e + qoff]
    const int qoff = seg ? -16335 : 1;
    const int E0   = seg ? (S - W) : 0;
    const int E1   = seg ? TE : (S + W);

    // ---- fill: aligned float4 copy of x range ----
    {
        const float4* __restrict__ xv = (const float4*)(xr + (seg ? 16320 : 0));
        float4* __restrict__ sv = (float4*)(sm + (seg ? 0 : 16));
        const int n4 = seg ? 4112 : 4113;
        #pragma unroll 4
        for (int i = tid; i < n4; i += NTH) sv[i] = xv[i];
    }
    // ---- reflection samples ----
    if (tid < PAD) {
        if (seg == 0) {
            sm[tid + 1] = 2.0f * xr[0] - xr[PAD - tid];          // e = tid
        } else {
            const int e = TE - PAD + tid;                        // [32783, 32798)
            sm[e - 16335] = 2.0f * xr[T_LEN - 1] - xr[65549 - e];
        }
    }
    __syncthreads();

    // ---------------- forward pass over [seg_lo, E1) ----------------
    {
        StP st = {0ull, 0ull};
        int c_lo, c_hi;
        if (seg == 0) {
            c_lo = tid ? (3 + tid * C) : 0;     // thread 0 absorbs [0,3)
            c_hi = min(3 + (tid + 1) * C, E1);
        } else {
            c_lo = S + tid * C;
            c_hi = min(c_lo + C, TE);
        }
        const bool act = c_lo < E1;
        if (act) fwd_ro(sm, max(E0, c_lo - W) + qoff, c_lo + qoff, st, cf);
        __syncthreads();                        // warm reads before chunk writes
        if (act) fwd_rw(sm, c_lo + qoff, c_hi + qoff, st, cf);
    }
    __syncthreads();

    // ---------------- backward pass over [seg_lo, seg_hi) -----------
    {
        StP st = {0ull, 0ull};
        const int lo_lim = seg ? S : 0;
        const int bc_hi = (seg ? (TE - 1) : (S - 1)) - tid * C;  // inclusive
        const int bc_lo = max(lo_lim, bc_hi - C + 1);
        const bool act = bc_hi >= lo_lim;
        if (act) {
            const int w_hi = min(E1 - 1, bc_hi + W);
            bwd_ro(sm, w_hi + qoff, bc_hi + 1 + qoff, st, cf);
        }
        __syncthreads();
        if (act) bwd_rw(sm, bc_hi + qoff, bc_lo + qoff, st, cf);
    }
    __syncthreads();

    // ---- output: aligned float4 copy (4096 groups per segment) ----
    {
        const int t0 = seg ? 16384 : 0;         // out base, %4==0
        const float4* __restrict__ s4 = (const float4*)(sm + (t0 + PAD + qoff));
        float4* __restrict__ o4 = (float4*)(out + (size_t)row * T_LEN + t0);
        #pragma unroll 4
        for (int i = tid; i < 4096; i += NTH) o4[i] = s4[i];
    }
}

extern "C" void kernel_launch(void* const* d_in, const int* in_sizes, int n_in,
                              void* d_out, int out_size) {
    const float* x = (const float*)d_in[0];
    float* out = (float*)d_out;
    const int rows = out_size / T_LEN;   // 512
    cudaFuncSetAttribute(filtfilt_r7_kernel,
                         cudaFuncAttributeMaxDynamicSharedMemorySize,
                         SMLEN * sizeof(float));
    filtfilt_r7_kernel<<<rows * 2, NTH, SMLEN * sizeof(float)>>>(x, out);
}

// round 8
// speedup vs baseline: 1.1339x; 1.1339x over previous
#include <cuda_runtime.h>

// filtfilt(butter(4)) over 512 rows x 32768 fp32 samples.
// R8 = R5 geometry (2 segments/row, 66KB smem, 3 blocks/SM, vectorized
// LDS/STS IIR, scalar fmaf recurrence) with NTH 128->256 and C 132->66:
// doubles resident warps per SMSP (3->6, occ 16.7%->33%) at ~constant total
// issued work (W trimmed 64->48; max pole 0.795 -> residual ~1.6e-5).
// All rounds show per-warp issue ~0.13/cyc (stall-dominated) and issue%
// monotone in warps/SMSP -> latency/occupancy-bound, so add warps.
// Split S=16399; seg0: xe(e)=sm[e+1], seg1: xe(e)=sm[e-16335].
// max|x| normalization skipped (linear pipeline; rounding-level change).

#define T_LEN  32768
#define PAD    15
#define TE     (T_LEN + 2 * PAD)   /* 32798 */
#define S      16399               /* split, ==3 mod 4 */
#define NTH    256
#define C      66
#define W      48
#define SMLEN  16480

#define B0f  0.0048243445989025905f
#define B1f  0.019297378395610362f
#define B2f  0.028946067593415543f
#define NA1f 2.369513007182038f      /* -a1 */
#define NA2f (-2.3139884144002064f)  /* -a2 */
#define NA3f 1.0546654058785661f     /* -a3 */
#define NA4f (-0.18737949236818502f) /* -a4 */

struct St { float z1, z2, z3, z4; };

__device__ __forceinline__ float stepf(float xv, St& s) {
    float y  = fmaf(B0f, xv, s.z1);
    float t1 = fmaf(B1f, xv, s.z2);
    float t2 = fmaf(B2f, xv, s.z3);
    float t3 = fmaf(B1f, xv, s.z4);   // b3 == b1
    float t4 = B0f * xv;              // b4 == b0
    s.z1 = fmaf(NA1f, y, t1);
    s.z2 = fmaf(NA2f, y, t2);
    s.z3 = fmaf(NA3f, y, t3);
    s.z4 = fmaf(NA4f, y, t4);
    return y;
}

// ascending over smem indices [i, end)
__device__ __forceinline__ void fwd_ro(const float* s, int i, int end, St& st) {
    for (; i < end && (i & 3); ++i) stepf(s[i], st);
    #pragma unroll 2
    for (; i + 4 <= end; i += 4) {
        float4 v = *(const float4*)(s + i);
        stepf(v.x, st); stepf(v.y, st); stepf(v.z, st); stepf(v.w, st);
    }
    for (; i < end; ++i) stepf(s[i], st);
}
__device__ __forceinline__ void fwd_rw(float* s, int i, int end, St& st) {
    for (; i < end && (i & 3); ++i) s[i] = stepf(s[i], st);
    #pragma unroll 2
    for (; i + 4 <= end; i += 4) {
        float4 v = *(float4*)(s + i);
        v.x = stepf(v.x, st); v.y = stepf(v.y, st);
        v.z = stepf(v.z, st); v.w = stepf(v.w, st);
        *(float4*)(s + i) = v;
    }
    for (; i < end; ++i) s[i] = stepf(s[i], st);
}
// descending over smem indices i down to lo (inclusive)
__device__ __forceinline__ void bwd_ro(const float* s, int i, int lo, St& st) {
    for (; i >= lo && ((i & 3) != 3); --i) stepf(s[i], st);
    #pragma unroll 2
    for (; i - 3 >= lo; i -= 4) {
        float4 v = *(const float4*)(s + i - 3);
        stepf(v.w, st); stepf(v.z, st); stepf(v.y, st); stepf(v.x, st);
    }
    for (; i >= lo; --i) stepf(s[i], st);
}
__device__ __forceinline__ void bwd_rw(float* s, int i, int lo, St& st) {
    for (; i >= lo && ((i & 3) != 3); --i) { s[i] = stepf(s[i], st); }
    #pragma unroll 2
    for (; i - 3 >= lo; i -= 4) {
        float4 v = *(float4*)(s + i - 3);
        v.w = stepf(v.w, st); v.z = stepf(v.z, st);
        v.y = stepf(v.y, st); v.x = stepf(v.x, st);
        *(float4*)(s + i - 3) = v;
    }
    for (; i >= lo; --i) s[i] = stepf(s[i], st);
}

__global__ void __launch_bounds__(NTH)
filtfilt_r8_kernel(const float* __restrict__ x, float* __restrict__ out) {
    extern __shared__ float sm[];
    const int tid = threadIdx.x;
    const int row = blockIdx.x >> 1;
    const int seg = blockIdx.x & 1;
    const float* __restrict__ xr = x + (size_t)row * T_LEN;

    // qoff: xe(e) = sm[e + qoff]
    const int qoff = seg ? -16335 : 1;
    const int E0   = seg ? (S - W) : 0;        // 16351 / 0
    const int E1   = seg ? TE : (S + W);       // 32798 / 16447

    // ---- fill: aligned float4 copy of x range ----
    {
        // seg0: x[0..16452) at sm[16+j];  seg1: x[16320..32768) at sm[j-16320]
        const float4* __restrict__ xv = (const float4*)(xr + (seg ? 16320 : 0));
        float4* __restrict__ sv = (float4*)(sm + (seg ? 0 : 16));
        const int n4 = seg ? 4112 : 4113;
        #pragma unroll 4
        for (int i = tid; i < n4; i += NTH) sv[i] = xv[i];
    }
    // ---- reflection samples ----
    if (tid < PAD) {
        if (seg == 0) {
            sm[tid + 1] = 2.0f * xr[0] - xr[PAD - tid];          // e = tid
        } else {
            const int e = TE - PAD + tid;                        // [32783, 32798)
            sm[e - 16335] = 2.0f * xr[T_LEN - 1] - xr[65549 - e];
        }
    }
    __syncthreads();

    // ---------------- forward pass over [seg_lo, E1) ----------------
    {
        St st = {0.f, 0.f, 0.f, 0.f};
        int c_lo, c_hi;
        if (seg == 0) {
            c_lo = tid ? (3 + tid * C) : 0;     // thread 0 absorbs [0,3)
            c_hi = min(3 + (tid + 1) * C, E1);
        } else {
            c_lo = S + tid * C;
            c_hi = min(c_lo + C, TE);
        }
        const bool act = c_lo < E1;
        if (act) fwd_ro(sm, max(E0, c_lo - W) + qoff, c_lo + qoff, st);
        __syncthreads();                        // warm reads before chunk writes
        if (act) fwd_rw(sm, c_lo + qoff, c_hi + qoff, st);
    }
    __syncthreads();

    // ---------------- backward pass over [seg_lo, seg_hi) -----------
    {
        St st = {0.f, 0.f, 0.f, 0.f};
        const int lo_lim = seg ? S : 0;
        const int bc_hi = (seg ? (TE - 1) : (S - 1)) - tid * C;  // inclusive
        const int bc_lo = max(lo_lim, bc_hi - C + 1);
        const bool act = bc_hi >= lo_lim;
        if (act) {
            const int w_hi = min(E1 - 1, bc_hi + W);
            bwd_ro(sm, w_hi + qoff, bc_hi + 1 + qoff, st);
        }
        __syncthreads();
        if (act) bwd_rw(sm, bc_hi + qoff, bc_lo + qoff, st);
    }
    __syncthreads();

    // ---- output: aligned float4 copy (4096 groups per segment) ----
    {
        const int t0 = seg ? 16384 : 0;         // out base, %4==0
        // smidx of (t0 + PAD): seg0 -> 16, seg1 -> 64; both %4==0
        const float4* __restrict__ s4 = (const float4*)(sm + (t0 + PAD + qoff));
        float4* __restrict__ o4 = (float4*)(out + (size_t)row * T_LEN + t0);
        #pragma unroll 4
        for (int i = tid; i < 4096; i += NTH) o4[i] = s4[i];
    }
}

extern "C" void kernel_launch(void* const* d_in, const int* in_sizes, int n_in,
                              void* d_out, int out_size) {
    const float* x = (const float*)d_in[0];
    float* out = (float*)d_out;
    const int rows = out_size / T_LEN;   // 512
    cudaFuncSetAttribute(filtfilt_r8_kernel,
                         cudaFuncAttributeMaxDynamicSharedMemorySize,
                         SMLEN * sizeof(float));
    filtfilt_r8_kernel<<<rows * 2, NTH, SMLEN * sizeof(float)>>>(x, out);
}